// round 4
// baseline (speedup 1.0000x reference)
#include <cuda_runtime.h>
#include <math.h>

// Problem constants
#define CIN    128     // channels per half
#define CMID   16      // c_mid
#define COUT   256     // dim (output channels)
#define HW     12544   // 112*112
#define WIDTH  112
#define NBLK   784     // 16 * 49 blocks

// Pooling segments for 16 -> 7 (overlapping avg pool)
__constant__ int   SEG_S[7] = {0, 2, 4, 6, 9, 11, 13};
__constant__ int   SEG_E[7] = {3, 5, 7, 10, 12, 14, 16};
__constant__ float SEG_I[7] = {1.f/3.f, 1.f/3.f, 1.f/3.f, 0.25f, 1.f/3.f, 1.f/3.f, 1.f/3.f};

// ---- packed f32x2 helpers (sm_103a FFMA2 path, PTX-only) ----
__device__ __forceinline__ unsigned long long pk2(float a, float b) {
    unsigned long long r;
    asm("mov.b64 %0, {%1, %2};" : "=l"(r) : "f"(a), "f"(b));
    return r;
}
__device__ __forceinline__ unsigned long long ffma2(unsigned long long a,
                                                    unsigned long long b,
                                                    unsigned long long c) {
    unsigned long long d;
    asm("fma.rn.f32x2 %0, %1, %2, %3;" : "=l"(d) : "l"(a), "l"(b), "l"(c));
    return d;
}
__device__ __forceinline__ float2 upk(unsigned long long v) {
    float2 f;
    asm("mov.b64 {%0, %1}, %2;" : "=f"(f.x), "=f"(f.y) : "l"(v));
    return f;
}

// Shared memory byte-offsets (doubles first for alignment)
#define FSTRIDE 257            // padded row stride (conflict-free pooling)
#define OFF_FSD   0                         // double[16*257]  f features (fp64)
#define OFF_CFD   (OFF_FSD  + 16*FSTRIDE*8) // double[49*16]   centers (fp64, normalized)
#define OFF_WSFD  (OFF_CFD  + 784*8)        // double[128*16]  f weights transposed (fp64)
#define OFF_WSV   (OFF_WSFD + 2048*8)       // float [128*16]  v weights transposed
#define OFF_PWT   (OFF_WSV  + 2048*4)       // float [16*256]  p weights transposed
#define OFF_VS    (OFF_PWT  + 4096*4)       // float [16*257]  v features
#define OFF_VC    (OFF_VS   + 16*FSTRIDE*4) // float [784]     value centers
#define OFF_AGN   (OFF_VC   + 784*4)        // float [784]     agg numerator -> agg
#define OFF_AGD   (OFF_AGN  + 784*4)        // float [52]      agg denominator
#define OFF_VBS   (OFF_AGD  + 52*4)         // float [16]
#define OFF_PBS   (OFF_VBS  + 16*4)         // float [256]
#define OFF_FBD   (OFF_PBS  + 256*4)        // double[16]
#define SMEM_BYTES (OFF_FBD + 16*8)

extern "C" __global__ void __launch_bounds__(256, 2)
lc_kernel(const float* __restrict__ x,   const float* __restrict__ fw,
          const float* __restrict__ fb,  const float* __restrict__ vw,
          const float* __restrict__ vb,  const float* __restrict__ pw,
          const float* __restrict__ pbg, const float* __restrict__ salpha,
          const float* __restrict__ sbeta, float* __restrict__ out)
{
    extern __shared__ char smraw[];
    double* fsd  = (double*)(smraw + OFF_FSD);
    double* cfd  = (double*)(smraw + OFF_CFD);
    double* wsfd = (double*)(smraw + OFF_WSFD);
    double* fbd  = (double*)(smraw + OFF_FBD);
    float*  wsv  = (float*)(smraw + OFF_WSV);
    float*  pwt  = (float*)(smraw + OFF_PWT);
    float*  vs   = (float*)(smraw + OFF_VS);
    float*  vc   = (float*)(smraw + OFF_VC);
    float*  agn  = (float*)(smraw + OFF_AGN);
    float*  agd  = (float*)(smraw + OFF_AGD);
    float*  vbs  = (float*)(smraw + OFF_VBS);
    float*  pbs  = (float*)(smraw + OFF_PBS);

    const int t = threadIdx.x;            // pixel index n = pr*16 + pc
    const int b = blockIdx.x;             // block = batch*49 + gx*7 + gy
    const int batch = b / 49;
    const int g = b - batch * 49;
    const int gx = g / 7, gy = g - (g / 7) * 7;
    const int pr = t >> 4, pc = t & 15;

    // ---- load weights into smem ----
    for (int i = t; i < 2048; i += 256) {
        int c = i >> 4, o = i & 15;
        wsfd[i] = (double)fw[o * CIN + c];
        wsv[i]  = vw[o * CIN + c];
    }
    for (int i = t; i < 4096; i += 256) {
        int cc = i >> 8, o = i & 255;
        pwt[i] = pw[o * CMID + cc];
    }
    if (t < 16) { fbd[t] = (double)fb[t]; vbs[t] = vb[t]; }
    pbs[t] = pbg[t];
    for (int i = t; i < 784; i += 256) agn[i] = 0.f;
    if (t < 49) agd[t] = 0.f;
    __syncthreads();

    // ---- Stage A: f (fp64 exact) and v (f32x2 fast) per pixel ----
    const float* xb = x + (size_t)batch * COUT * HW
                        + (size_t)(gx * 16 + pr) * WIDTH + (gy * 16 + pc);
    double fd[16];
    unsigned long long va[8];
    #pragma unroll
    for (int j = 0; j < 16; j++) fd[j] = 0.0;
    #pragma unroll
    for (int j = 0; j < 8; j++) va[j] = 0ull;

    #pragma unroll 4
    for (int c = 0; c < CIN; c++) {
        float x1 = __ldg(xb + (size_t)c * HW);
        float x2 = __ldg(xb + (size_t)(c + CIN) * HW);
        double x1d = (double)x1;
        unsigned long long x2d = pk2(x2, x2);
        const double2* wf = (const double2*)(wsfd + c * 16);
        const ulonglong2* wv = (const ulonglong2*)(wsv + c * 16);
        #pragma unroll
        for (int j = 0; j < 8; j++) {
            double2 w = wf[j];
            fd[2*j]   = fma(x1d, w.x, fd[2*j]);
            fd[2*j+1] = fma(x1d, w.y, fd[2*j+1]);
        }
        #pragma unroll
        for (int j = 0; j < 4; j++) {
            ulonglong2 bwt = wv[j];
            va[2*j]   = ffma2(x2d, bwt.x, va[2*j]);
            va[2*j+1] = ffma2(x2d, bwt.y, va[2*j+1]);
        }
    }
    #pragma unroll
    for (int cc = 0; cc < 16; cc++)
        fsd[cc * FSTRIDE + t] = fd[cc] + fbd[cc];
    #pragma unroll
    for (int j = 0; j < 8; j++) {
        float2 vv = upk(va[j]);
        vs[(2*j)   * FSTRIDE + t] = vv.x + vbs[2*j];
        vs[(2*j+1) * FSTRIDE + t] = vv.y + vbs[2*j+1];
    }
    __syncthreads();

    // ---- Stage B: pooled centers (fp64) and value centers (fp32) ----
    for (int it = t; it < 784; it += 256) {
        int m = it >> 4, cc = it & 15;
        int i = m / 7, jj = m - i * 7;
        double ssum = 0.0;
        for (int r = SEG_S[i]; r < SEG_E[i]; r++)
            for (int q = SEG_S[jj]; q < SEG_E[jj]; q++)
                ssum += fsd[cc * FSTRIDE + r * 16 + q];
        cfd[it] = ssum * (double)SEG_I[i] * (double)SEG_I[jj];
    }
    for (int it = t; it < 784; it += 256) {
        int m = it >> 4, cc = it & 15;
        int i = m / 7, jj = m - i * 7;
        float ssum = 0.f;
        for (int r = SEG_S[i]; r < SEG_E[i]; r++)
            for (int q = SEG_S[jj]; q < SEG_E[jj]; q++)
                ssum += vs[cc * FSTRIDE + r * 16 + q];
        vc[it] = ssum * SEG_I[i] * SEG_I[jj];
    }
    __syncthreads();

    // ---- normalize cluster centers in place (fp64) ----
    if (t < 49) {
        double ss = 0.0;
        #pragma unroll
        for (int cc = 0; cc < 16; cc++) { double v = cfd[t*16+cc]; ss = fma(v, v, ss); }
        double inv = 1.0 / fmax(sqrt(ss), 1e-12);
        #pragma unroll
        for (int cc = 0; cc < 16; cc++) cfd[t*16+cc] *= inv;
    }
    __syncthreads();

    // ---- Stage C: exact fp64 sim; top-3 by z; fp32-sigmoid collapse tie rule ----
    double ffd[16];
    #pragma unroll
    for (int cc = 0; cc < 16; cc++) ffd[cc] = fsd[cc * FSTRIDE + t];
    double ssd = 0.0;
    #pragma unroll
    for (int cc = 0; cc < 16; cc++) ssd = fma(ffd[cc], ffd[cc], ssd);
    double invf = 1.0 / fmax(sqrt(ssd), 1e-12);
    #pragma unroll
    for (int cc = 0; cc < 16; cc++) ffd[cc] *= invf;
    const double alpha = (double)__ldg(salpha);
    const double beta  = (double)__ldg(sbeta);

    double z1 = -1e300, z2 = -1e300, z3 = -1e300;
    int m1 = 0, m2 = 0, m3 = 0;
    for (int m = 0; m < 49; m++) {
        const double2* cr = (const double2*)(cfd + m * 16);
        double dot = 0.0;
        #pragma unroll
        for (int q = 0; q < 8; q++) {
            double2 w = cr[q];
            dot = fma(w.x, ffd[2*q], dot);
            dot = fma(w.y, ffd[2*q+1], dot);
        }
        double z = beta + alpha * dot;
        if (z > z1)      { z3 = z2; m3 = m2; z2 = z1; m2 = m1; z1 = z; m1 = m; }
        else if (z > z2) { z3 = z2; m3 = m2; z2 = z;  m2 = m; }
        else if (z > z3) { z3 = z;  m3 = m; }
    }
    // fp32 sigmoids of the top-3: monotone rounding => s1f >= s2f >= s3f.
    // jnp.argmax on fp32 sigmoid picks the FIRST (lowest) index among equal maxima.
    float s1f = (float)(1.0 / (1.0 + exp(-z1)));
    float s2f = (float)(1.0 / (1.0 + exp(-z2)));
    float s3f = (float)(1.0 / (1.0 + exp(-z3)));
    int bm = m1;
    if (s2f == s1f && m2 < bm) bm = m2;
    if (s3f == s1f && m3 < bm) bm = m3;
    const float s = s1f;

    // ---- aggregate: agg[m] = (sum s*v + value_centers) / (sum s + 1) ----
    atomicAdd(&agd[bm], s);
    #pragma unroll
    for (int cc = 0; cc < 16; cc++)
        atomicAdd(&agn[bm * 16 + cc], s * vs[cc * FSTRIDE + t]);
    __syncthreads();

    for (int it = t; it < 784; it += 256) {
        int m = it >> 4;
        agn[it] = (agn[it] + vc[it]) / (agd[m] + 1.f);
    }
    __syncthreads();

    // ---- Stage D: mid[n] = s*agg[m*], then y = pw @ mid + pb (f32x2) ----
    unsigned long long ocd[16];
    #pragma unroll
    for (int cc = 0; cc < 16; cc++) {
        float o = s * agn[bm * 16 + cc];
        ocd[cc] = pk2(o, o);
    }
    float* yb = out + (size_t)batch * COUT * HW
                    + (size_t)(gx * 16 + pr) * WIDTH + (gy * 16 + pc);
    #pragma unroll 4
    for (int og = 0; og < 64; og++) {
        ulonglong2 pbv = *(const ulonglong2*)(pbs + og * 4);
        unsigned long long a0 = pbv.x, a1 = pbv.y;
        #pragma unroll
        for (int cc = 0; cc < 16; cc++) {
            ulonglong2 w = *(const ulonglong2*)(pwt + cc * 256 + og * 4);
            a0 = ffma2(ocd[cc], w.x, a0);
            a1 = ffma2(ocd[cc], w.y, a1);
        }
        float2 r0 = upk(a0), r1 = upk(a1);
        yb[(size_t)(og*4 + 0) * HW] = r0.x;
        yb[(size_t)(og*4 + 1) * HW] = r0.y;
        yb[(size_t)(og*4 + 2) * HW] = r1.x;
        yb[(size_t)(og*4 + 3) * HW] = r1.y;
    }
}

extern "C" void kernel_launch(void* const* d_in, const int* in_sizes, int n_in,
                              void* d_out, int out_size) {
    const float* x   = (const float*)d_in[0];
    const float* fw  = (const float*)d_in[1];
    const float* fb  = (const float*)d_in[2];
    const float* vw  = (const float*)d_in[3];
    const float* vb  = (const float*)d_in[4];
    const float* pw  = (const float*)d_in[5];
    const float* pb  = (const float*)d_in[6];
    const float* sa  = (const float*)d_in[7];
    const float* sb  = (const float*)d_in[8];
    float* out = (float*)d_out;

    cudaFuncSetAttribute(lc_kernel, cudaFuncAttributeMaxDynamicSharedMemorySize,
                         SMEM_BYTES);
    lc_kernel<<<NBLK, 256, SMEM_BYTES>>>(x, fw, fb, vw, vb, pw, pb, sa, sb, out);
}

// round 5
// speedup vs baseline: 2.5419x; 2.5419x over previous
#include <cuda_runtime.h>
#include <math.h>

// Problem constants
#define CIN    128     // channels per half
#define CMID   16      // c_mid
#define COUT   256     // dim (output channels)
#define HW     12544   // 112*112
#define WIDTH  112
#define NBLK   784     // 16 * 49 blocks

// Pooling segments for 16 -> 7 (overlapping avg pool)
__constant__ int   SEG_S[7] = {0, 2, 4, 6, 9, 11, 13};
__constant__ int   SEG_E[7] = {3, 5, 7, 10, 12, 14, 16};
__constant__ float SEG_I[7] = {1.f/3.f, 1.f/3.f, 1.f/3.f, 0.25f, 1.f/3.f, 1.f/3.f, 1.f/3.f};

// ---- packed f32x2 helpers (sm_103a FFMA2 path, PTX-only) ----
__device__ __forceinline__ unsigned long long pk2(float a, float b) {
    unsigned long long r;
    asm("mov.b64 %0, {%1, %2};" : "=l"(r) : "f"(a), "f"(b));
    return r;
}
__device__ __forceinline__ unsigned long long ffma2(unsigned long long a,
                                                    unsigned long long b,
                                                    unsigned long long c) {
    unsigned long long d;
    asm("fma.rn.f32x2 %0, %1, %2, %3;" : "=l"(d) : "l"(a), "l"(b), "l"(c));
    return d;
}
__device__ __forceinline__ float2 upk(unsigned long long v) {
    float2 f;
    asm("mov.b64 {%0, %1}, %2;" : "=f"(f.x), "=f"(f.y) : "l"(v));
    return f;
}

// ---- float-float accumulate: exact twoProd + twoSum (all on fp32 fma pipe) ----
__device__ __forceinline__ void dfacc(float& hi, float& lo, float x, float w) {
    float ph = __fmul_rn(x, w);
    float pl = __fmaf_rn(x, w, -ph);            // exact product residual
    float s  = __fadd_rn(hi, ph);               // twoSum(hi, ph)
    float bb = __fsub_rn(s, hi);
    float e  = __fadd_rn(__fsub_rn(hi, __fsub_rn(s, bb)), __fsub_rn(ph, bb));
    hi = s;
    lo = __fadd_rn(lo, __fadd_rn(e, pl));
}

// Shared memory byte-offsets
#define FSTRIDE 257
#define OFF_FSD   0                          // double[16*257] f features (exact)
#define OFF_CFD   (OFF_FSD  + 16*FSTRIDE*8)  // double[49*16]  normalized centers
#define OFF_PWT   (OFF_CFD  + 784*8)         // float [16*256] p weights T
#define OFF_WSF   (OFF_PWT  + 4096*4)        // float [128*16] f weights T
#define OFF_WSV   (OFF_WSF  + 2048*4)        // float [128*16] v weights T
#define OFF_VS    (OFF_WSV  + 2048*4)        // float [16*257] v features
#define OFF_CF32  (OFF_VS   + 16*FSTRIDE*4)  // float [49*16]  fp32 copy of centers
#define OFF_VC    (OFF_CF32 + 784*4)         // float [784]    value centers
#define OFF_AGN   (OFF_VC   + 784*4)         // float [784]    agg numerator -> agg
#define OFF_AGD   (OFF_AGN  + 784*4)         // float [52]
#define OFF_FBS   (OFF_AGD  + 52*4)          // float [16]
#define OFF_VBS   (OFF_FBS  + 16*4)          // float [16]
#define OFF_PBS   (OFF_VBS  + 16*4)          // float [256]
#define SMEM_BYTES (OFF_PBS + 256*4)

extern "C" __global__ void __launch_bounds__(256, 2)
lc_kernel(const float* __restrict__ x,   const float* __restrict__ fw,
          const float* __restrict__ fb,  const float* __restrict__ vw,
          const float* __restrict__ vb,  const float* __restrict__ pw,
          const float* __restrict__ pbg, const float* __restrict__ salpha,
          const float* __restrict__ sbeta, float* __restrict__ out)
{
    extern __shared__ char smraw[];
    double* fsd  = (double*)(smraw + OFF_FSD);
    double* cfd  = (double*)(smraw + OFF_CFD);
    float*  pwt  = (float*)(smraw + OFF_PWT);
    float*  wsf  = (float*)(smraw + OFF_WSF);
    float*  wsv  = (float*)(smraw + OFF_WSV);
    float*  vs   = (float*)(smraw + OFF_VS);
    float*  cf32 = (float*)(smraw + OFF_CF32);
    float*  vc   = (float*)(smraw + OFF_VC);
    float*  agn  = (float*)(smraw + OFF_AGN);
    float*  agd  = (float*)(smraw + OFF_AGD);
    float*  fbs  = (float*)(smraw + OFF_FBS);
    float*  vbs  = (float*)(smraw + OFF_VBS);
    float*  pbs  = (float*)(smraw + OFF_PBS);

    const int t = threadIdx.x;            // pixel index n = pr*16 + pc
    const int b = blockIdx.x;             // block = batch*49 + gx*7 + gy
    const int batch = b / 49;
    const int g = b - batch * 49;
    const int gx = g / 7, gy = g - (g / 7) * 7;
    const int pr = t >> 4, pc = t & 15;

    // ---- load weights into smem ----
    for (int i = t; i < 2048; i += 256) {
        int c = i >> 4, o = i & 15;
        wsf[i] = fw[o * CIN + c];
        wsv[i] = vw[o * CIN + c];
    }
    for (int i = t; i < 4096; i += 256) {
        int cc = i >> 8, o = i & 255;
        pwt[i] = pw[o * CMID + cc];
    }
    if (t < 16) { fbs[t] = fb[t]; vbs[t] = vb[t]; }
    pbs[t] = pbg[t];
    for (int i = t; i < 784; i += 256) agn[i] = 0.f;
    if (t < 49) agd[t] = 0.f;
    __syncthreads();

    // ---- Stage A: f via float-float (fma pipe, ~1e-12 accurate), v via f32x2 ----
    const float* xb = x + (size_t)batch * COUT * HW
                        + (size_t)(gx * 16 + pr) * WIDTH + (gy * 16 + pc);
    float fhi[16], flo[16];
    unsigned long long va[8];
    #pragma unroll
    for (int j = 0; j < 16; j++) { fhi[j] = 0.f; flo[j] = 0.f; }
    #pragma unroll
    for (int j = 0; j < 8; j++) va[j] = 0ull;

    #pragma unroll 4
    for (int c = 0; c < CIN; c++) {
        float x1 = __ldg(xb + (size_t)c * HW);
        float x2 = __ldg(xb + (size_t)(c + CIN) * HW);
        const float4* wf = (const float4*)(wsf + c * 16);
        unsigned long long x2d = pk2(x2, x2);
        const ulonglong2* wv = (const ulonglong2*)(wsv + c * 16);
        #pragma unroll
        for (int q = 0; q < 4; q++) {
            float4 w = wf[q];
            dfacc(fhi[4*q+0], flo[4*q+0], x1, w.x);
            dfacc(fhi[4*q+1], flo[4*q+1], x1, w.y);
            dfacc(fhi[4*q+2], flo[4*q+2], x1, w.z);
            dfacc(fhi[4*q+3], flo[4*q+3], x1, w.w);
        }
        #pragma unroll
        for (int j = 0; j < 4; j++) {
            ulonglong2 bwt = wv[j];
            va[2*j]   = ffma2(x2d, bwt.x, va[2*j]);
            va[2*j+1] = ffma2(x2d, bwt.y, va[2*j+1]);
        }
    }
    #pragma unroll
    for (int cc = 0; cc < 16; cc++)
        fsd[cc * FSTRIDE + t] = ((double)fhi[cc] + (double)flo[cc]) + (double)fbs[cc];
    #pragma unroll
    for (int j = 0; j < 8; j++) {
        float2 vv = upk(va[j]);
        vs[(2*j)   * FSTRIDE + t] = vv.x + vbs[2*j];
        vs[(2*j+1) * FSTRIDE + t] = vv.y + vbs[2*j+1];
    }
    __syncthreads();

    // ---- Stage B: pooled centers (fp64, small) and value centers (fp32) ----
    for (int it = t; it < 784; it += 256) {
        int m = it >> 4, cc = it & 15;
        int i = m / 7, jj = m - i * 7;
        double ssum = 0.0;
        for (int r = SEG_S[i]; r < SEG_E[i]; r++)
            for (int q = SEG_S[jj]; q < SEG_E[jj]; q++)
                ssum += fsd[cc * FSTRIDE + r * 16 + q];
        cfd[it] = ssum * (double)SEG_I[i] * (double)SEG_I[jj];
    }
    for (int it = t; it < 784; it += 256) {
        int m = it >> 4, cc = it & 15;
        int i = m / 7, jj = m - i * 7;
        float ssum = 0.f;
        for (int r = SEG_S[i]; r < SEG_E[i]; r++)
            for (int q = SEG_S[jj]; q < SEG_E[jj]; q++)
                ssum += vs[cc * FSTRIDE + r * 16 + q];
        vc[it] = ssum * SEG_I[i] * SEG_I[jj];
    }
    __syncthreads();

    // ---- normalize centers (fp64, 49 threads) + fp32 copy ----
    if (t < 49) {
        double ss = 0.0;
        #pragma unroll
        for (int cc = 0; cc < 16; cc++) { double v = cfd[t*16+cc]; ss = fma(v, v, ss); }
        double inv = 1.0 / fmax(sqrt(ss), 1e-12);
        #pragma unroll
        for (int cc = 0; cc < 16; cc++) {
            double nv = cfd[t*16+cc] * inv;
            cfd[t*16+cc]  = nv;
            cf32[t*16+cc] = (float)nv;
        }
    }
    __syncthreads();

    // ---- Stage C: normalize f (fp64, few ops); fp32 dot prefilter; fp64 top-3 ----
    double ffd[16];
    float  ffn[16];
    {
        double ss = 0.0;
        #pragma unroll
        for (int cc = 0; cc < 16; cc++) {
            ffd[cc] = fsd[cc * FSTRIDE + t];
            ss = fma(ffd[cc], ffd[cc], ss);
        }
        double inv = 1.0 / fmax(sqrt(ss), 1e-12);
        #pragma unroll
        for (int cc = 0; cc < 16; cc++) {
            ffd[cc] *= inv;
            ffn[cc] = (float)ffd[cc];
        }
    }
    const double alpha = (double)__ldg(salpha);
    const double beta  = (double)__ldg(sbeta);

    // pass 1: fp32 dot max
    float mx32 = -1e30f;
    for (int m = 0; m < 49; m++) {
        const float4* cr = (const float4*)(cf32 + m * 16);
        float dot = 0.f;
        #pragma unroll
        for (int q = 0; q < 4; q++) {
            float4 w = cr[q];
            dot = __fmaf_rn(w.x, ffn[4*q+0], dot);
            dot = __fmaf_rn(w.y, ffn[4*q+1], dot);
            dot = __fmaf_rn(w.z, ffn[4*q+2], dot);
            dot = __fmaf_rn(w.w, ffn[4*q+3], dot);
        }
        mx32 = fmaxf(mx32, dot);
    }
    // pass 2: fp64 recompute only near-max clusters; track top-3 exact z
    const float thr = mx32 - 1e-4f;
    double z1 = -1e300, z2 = -1e300, z3 = -1e300;
    int m1 = 0, m2 = 0, m3 = 0;
    for (int m = 0; m < 49; m++) {
        const float4* cr = (const float4*)(cf32 + m * 16);
        float dot = 0.f;
        #pragma unroll
        for (int q = 0; q < 4; q++) {
            float4 w = cr[q];
            dot = __fmaf_rn(w.x, ffn[4*q+0], dot);
            dot = __fmaf_rn(w.y, ffn[4*q+1], dot);
            dot = __fmaf_rn(w.z, ffn[4*q+2], dot);
            dot = __fmaf_rn(w.w, ffn[4*q+3], dot);
        }
        if (dot >= thr) {
            const double2* crd = (const double2*)(cfd + m * 16);
            double dd = 0.0;
            #pragma unroll
            for (int q = 0; q < 8; q++) {
                double2 w = crd[q];
                dd = fma(w.x, ffd[2*q],   dd);
                dd = fma(w.y, ffd[2*q+1], dd);
            }
            double z = beta + alpha * dd;
            if (z > z1)      { z3 = z2; m3 = m2; z2 = z1; m2 = m1; z1 = z; m1 = m; }
            else if (z > z2) { z3 = z2; m3 = m2; z2 = z;  m2 = m; }
            else if (z > z3) { z3 = z;  m3 = m; }
        }
    }
    // fp32-sigmoid collapse tie rule (identical to the passing round)
    float s1f = (float)(1.0 / (1.0 + exp(-z1)));
    int bm = m1;
    if (z1 - z2 < 1e-5) {
        float s2f = (float)(1.0 / (1.0 + exp(-z2)));
        if (s2f == s1f && m2 < bm) bm = m2;
        if (z1 - z3 < 1e-5) {
            float s3f = (float)(1.0 / (1.0 + exp(-z3)));
            if (s3f == s1f && m3 < bm) bm = m3;
        }
    }
    const float s = s1f;

    // ---- aggregate: agg[m] = (sum s*v + value_centers) / (sum s + 1) ----
    atomicAdd(&agd[bm], s);
    #pragma unroll
    for (int cc = 0; cc < 16; cc++)
        atomicAdd(&agn[bm * 16 + cc], s * vs[cc * FSTRIDE + t]);
    __syncthreads();

    for (int it = t; it < 784; it += 256) {
        int m = it >> 4;
        agn[it] = (agn[it] + vc[it]) / (agd[m] + 1.f);
    }
    __syncthreads();

    // ---- Stage D: mid[n] = s*agg[m*], then y = pw @ mid + pb (f32x2) ----
    unsigned long long ocd[16];
    #pragma unroll
    for (int cc = 0; cc < 16; cc++) {
        float o = s * agn[bm * 16 + cc];
        ocd[cc] = pk2(o, o);
    }
    float* yb = out + (size_t)batch * COUT * HW
                    + (size_t)(gx * 16 + pr) * WIDTH + (gy * 16 + pc);
    #pragma unroll 4
    for (int og = 0; og < 64; og++) {
        ulonglong2 pbv = *(const ulonglong2*)(pbs + og * 4);
        unsigned long long a0 = pbv.x, a1 = pbv.y;
        #pragma unroll
        for (int cc = 0; cc < 16; cc++) {
            ulonglong2 w = *(const ulonglong2*)(pwt + cc * 256 + og * 4);
            a0 = ffma2(ocd[cc], w.x, a0);
            a1 = ffma2(ocd[cc], w.y, a1);
        }
        float2 r0 = upk(a0), r1 = upk(a1);
        yb[(size_t)(og*4 + 0) * HW] = r0.x;
        yb[(size_t)(og*4 + 1) * HW] = r0.y;
        yb[(size_t)(og*4 + 2) * HW] = r1.x;
        yb[(size_t)(og*4 + 3) * HW] = r1.y;
    }
}

extern "C" void kernel_launch(void* const* d_in, const int* in_sizes, int n_in,
                              void* d_out, int out_size) {
    const float* x   = (const float*)d_in[0];
    const float* fw  = (const float*)d_in[1];
    const float* fb  = (const float*)d_in[2];
    const float* vw  = (const float*)d_in[3];
    const float* vb  = (const float*)d_in[4];
    const float* pw  = (const float*)d_in[5];
    const float* pb  = (const float*)d_in[6];
    const float* sa  = (const float*)d_in[7];
    const float* sb  = (const float*)d_in[8];
    float* out = (float*)d_out;

    cudaFuncSetAttribute(lc_kernel, cudaFuncAttributeMaxDynamicSharedMemorySize,
                         SMEM_BYTES);
    lc_kernel<<<NBLK, 256, SMEM_BYTES>>>(x, fw, fb, vw, vb, pw, pb, sa, sb, out);
}

// round 6
// speedup vs baseline: 2.8088x; 1.1050x over previous
#include <cuda_runtime.h>
#include <math.h>

// Problem constants
#define CIN    128
#define CMID   16
#define COUT   256
#define HW     12544
#define WIDTH  112
#define NBLK   784

// Pooling segments 16 -> 7 (overlapping avg pool)
__constant__ int   SEG_S[7] = {0, 2, 4, 6, 9, 11, 13};
__constant__ int   SEG_E[7] = {3, 5, 7, 10, 12, 14, 16};
__constant__ float SEG_I[7] = {1.f/3.f, 1.f/3.f, 1.f/3.f, 0.25f, 1.f/3.f, 1.f/3.f, 1.f/3.f};

// ---- packed f32x2 helpers (sm_103a, PTX-only) ----
__device__ __forceinline__ unsigned long long pk2(float a, float b) {
    unsigned long long r;
    asm("mov.b64 %0, {%1, %2};" : "=l"(r) : "f"(a), "f"(b));
    return r;
}
__device__ __forceinline__ unsigned long long ffma2(unsigned long long a,
                                                    unsigned long long b,
                                                    unsigned long long c) {
    unsigned long long d;
    asm("fma.rn.f32x2 %0, %1, %2, %3;" : "=l"(d) : "l"(a), "l"(b), "l"(c));
    return d;
}
__device__ __forceinline__ unsigned long long fmul2(unsigned long long a,
                                                    unsigned long long b) {
    unsigned long long d;
    asm("mul.rn.f32x2 %0, %1, %2;" : "=l"(d) : "l"(a), "l"(b));
    return d;
}
__device__ __forceinline__ unsigned long long fadd2(unsigned long long a,
                                                    unsigned long long b) {
    unsigned long long d;
    asm("add.rn.f32x2 %0, %1, %2;" : "=l"(d) : "l"(a), "l"(b));
    return d;
}
__device__ __forceinline__ float2 upk(unsigned long long v) {
    float2 f;
    asm("mov.b64 {%0, %1}, %2;" : "=f"(f.x), "=f"(f.y) : "l"(v));
    return f;
}

#define SGNMASK 0x8000000080000000ULL
#define OFFSET_F 16384.0f

// Exact compensated accumulate, packed 2 channels.
// Precondition: |hi| >= |ph| (guaranteed by OFFSET_F init) -> fast2sum exact.
__device__ __forceinline__ void dfacc2(unsigned long long& hi, unsigned long long& lo,
                                       unsigned long long xd, unsigned long long w) {
    unsigned long long ph = fmul2(xd, w);
    unsigned long long pl = ffma2(xd, w, ph ^ SGNMASK);  // exact product residual
    unsigned long long s  = fadd2(hi, ph);
    unsigned long long d  = fadd2(hi, s ^ SGNMASK);      // hi - s (exact, Sterbenz)
    unsigned long long e  = fadd2(d, ph);                // exact fast2sum error
    lo = fadd2(lo, fadd2(e, pl));
    hi = s;
}

// Shared memory byte-offsets
#define FSTRIDE 258            // double stride for f features (conflict-dodged)
#define VSTRIDE 257
#define OFF_FSD   0                          // double[16*258] f features (exact)
#define OFF_CFD   (OFF_FSD + 16*FSTRIDE*8)   // double[784]    normalized centers
#define OFF_WBUF  (OFF_CFD + 784*8)          // float[4096] time-shared:
                                             //   stage A: wsf[0:2048] wsv[2048:4096]
                                             //   stage B/C: vc[0:784] cf32[784:1568]
                                             //   stage D: pwt[0:4096]
#define OFF_VS    (OFF_WBUF + 4096*4)        // float[16*257]  v features
#define OFF_AGN   (OFF_VS  + 16*VSTRIDE*4)   // float[784]
#define OFF_AGD   (OFF_AGN + 784*4)          // float[52]
#define OFF_FBS   (OFF_AGD + 52*4)           // float[16]
#define OFF_VBS   (OFF_FBS + 16*4)           // float[16]
#define SMEM_BYTES (OFF_VBS + 16*4)          // 75,600 B -> 3 CTAs/SM

extern "C" __global__ void __launch_bounds__(256, 3)
lc_kernel(const float* __restrict__ x,   const float* __restrict__ fw,
          const float* __restrict__ fb,  const float* __restrict__ vw,
          const float* __restrict__ vb,  const float* __restrict__ pw,
          const float* __restrict__ pbg, const float* __restrict__ salpha,
          const float* __restrict__ sbeta, float* __restrict__ out)
{
    extern __shared__ char smraw[];
    double* fsd  = (double*)(smraw + OFF_FSD);
    double* cfd  = (double*)(smraw + OFF_CFD);
    float*  wbuf = (float*)(smraw + OFF_WBUF);
    float*  vs   = (float*)(smraw + OFF_VS);
    float*  agn  = (float*)(smraw + OFF_AGN);
    float*  agd  = (float*)(smraw + OFF_AGD);
    float*  fbs  = (float*)(smraw + OFF_FBS);
    float*  vbs  = (float*)(smraw + OFF_VBS);
    float*  wsf  = wbuf;             // stage A
    float*  wsv  = wbuf + 2048;      // stage A
    float*  vc   = wbuf;             // stages B..merge
    float*  cf32 = wbuf + 784;       // stages norm..C
    float*  pwt  = wbuf;             // stage D

    const int t = threadIdx.x;
    const int b = blockIdx.x;
    const int batch = b / 49;
    const int g = b - batch * 49;
    const int gx = g / 7, gy = g - (g / 7) * 7;
    const int pr = t >> 4, pc = t & 15;

    // ---- stage A weights into smem ----
    for (int i = t; i < 2048; i += 256) {
        int c = i >> 4, o = i & 15;
        wsf[i] = fw[o * CIN + c];
        wsv[i] = vw[o * CIN + c];
    }
    if (t < 16) { fbs[t] = fb[t]; vbs[t] = vb[t]; }
    for (int i = t; i < 784; i += 256) agn[i] = 0.f;
    if (t < 49) agd[t] = 0.f;
    __syncthreads();

    // ---- Stage A: f via packed offset-fast2sum df; v via packed fma ----
    const float* xb = x + (size_t)batch * COUT * HW
                        + (size_t)(gx * 16 + pr) * WIDTH + (gy * 16 + pc);
    unsigned long long fhi[8], flo[8], va[8];
    #pragma unroll
    for (int j = 0; j < 8; j++) {
        fhi[j] = pk2(OFFSET_F, OFFSET_F);
        flo[j] = 0ull;
        va[j]  = 0ull;
    }

    #pragma unroll 4
    for (int c = 0; c < CIN; c++) {
        float x1 = __ldg(xb + (size_t)c * HW);
        float x2 = __ldg(xb + (size_t)(c + CIN) * HW);
        unsigned long long x1d = pk2(x1, x1);
        unsigned long long x2d = pk2(x2, x2);
        const ulonglong2* wf = (const ulonglong2*)(wsf + c * 16);
        const ulonglong2* wv = (const ulonglong2*)(wsv + c * 16);
        #pragma unroll
        for (int j = 0; j < 4; j++) {
            ulonglong2 a = wf[j];
            dfacc2(fhi[2*j],   flo[2*j],   x1d, a.x);
            dfacc2(fhi[2*j+1], flo[2*j+1], x1d, a.y);
            ulonglong2 bwt = wv[j];
            va[2*j]   = ffma2(x2d, bwt.x, va[2*j]);
            va[2*j+1] = ffma2(x2d, bwt.y, va[2*j+1]);
        }
    }
    #pragma unroll
    for (int j = 0; j < 8; j++) {
        float2 h = upk(fhi[j]), l = upk(flo[j]);
        // hi - OFFSET is exact (Sterbenz)
        fsd[(2*j)   * FSTRIDE + t] =
            ((double)__fadd_rn(h.x, -OFFSET_F) + (double)l.x) + (double)fbs[2*j];
        fsd[(2*j+1) * FSTRIDE + t] =
            ((double)__fadd_rn(h.y, -OFFSET_F) + (double)l.y) + (double)fbs[2*j+1];
        float2 vv = upk(va[j]);
        vs[(2*j)   * VSTRIDE + t] = vv.x + vbs[2*j];
        vs[(2*j+1) * VSTRIDE + t] = vv.y + vbs[2*j+1];
    }
    __syncthreads();

    // ---- Stage B: pooled centers (fp64) and value centers (fp32) ----
    // (overwrites the stage-A weight buffer: vc = wbuf[0:784])
    for (int it = t; it < 784; it += 256) {
        int m = it >> 4, cc = it & 15;
        int i = m / 7, jj = m - i * 7;
        double ssum = 0.0;
        for (int r = SEG_S[i]; r < SEG_E[i]; r++)
            for (int q = SEG_S[jj]; q < SEG_E[jj]; q++)
                ssum += fsd[cc * FSTRIDE + r * 16 + q];
        cfd[it] = ssum * (double)SEG_I[i] * (double)SEG_I[jj];
    }
    for (int it = t; it < 784; it += 256) {
        int m = it >> 4, cc = it & 15;
        int i = m / 7, jj = m - i * 7;
        float ssum = 0.f;
        for (int r = SEG_S[i]; r < SEG_E[i]; r++)
            for (int q = SEG_S[jj]; q < SEG_E[jj]; q++)
                ssum += vs[cc * VSTRIDE + r * 16 + q];
        vc[it] = ssum * SEG_I[i] * SEG_I[jj];
    }
    __syncthreads();

    // ---- normalize cluster centers (fp64) + fp32 copy for prefilter ----
    if (t < 49) {
        double ss = 0.0;
        #pragma unroll
        for (int cc = 0; cc < 16; cc++) { double v = cfd[t*16+cc]; ss = fma(v, v, ss); }
        double inv = 1.0 / fmax(sqrt(ss), 1e-12);
        #pragma unroll
        for (int cc = 0; cc < 16; cc++) {
            double nv = cfd[t*16+cc] * inv;
            cfd[t*16+cc]  = nv;
            cf32[t*16+cc] = (float)nv;
        }
    }
    __syncthreads();

    // ---- Stage C: fp32 prefilter dots; fp64 exact top-3 on near-max set ----
    float ffn[16];
    double invf;
    {
        double ss = 0.0;
        #pragma unroll
        for (int cc = 0; cc < 16; cc++) {
            double v = fsd[cc * FSTRIDE + t];
            ffn[cc] = (float)v;
            ss = fma(v, v, ss);
        }
        invf = 1.0 / fmax(sqrt(ss), 1e-12);
        float invff = (float)invf;
        #pragma unroll
        for (int cc = 0; cc < 16; cc++) ffn[cc] *= invff;
    }
    const double alpha = (double)__ldg(salpha);
    const double beta  = (double)__ldg(sbeta);

    // pass 1: fp32 dot max
    float mx32 = -1e30f;
    for (int m = 0; m < 49; m++) {
        const float4* cr = (const float4*)(cf32 + m * 16);
        float dot = 0.f;
        #pragma unroll
        for (int q = 0; q < 4; q++) {
            float4 w = cr[q];
            dot = __fmaf_rn(w.x, ffn[4*q+0], dot);
            dot = __fmaf_rn(w.y, ffn[4*q+1], dot);
            dot = __fmaf_rn(w.z, ffn[4*q+2], dot);
            dot = __fmaf_rn(w.w, ffn[4*q+3], dot);
        }
        mx32 = fmaxf(mx32, dot);
    }
    // pass 2: exact z for near-max clusters only (operands reloaded from smem)
    const float thr = mx32 - 1e-4f;
    double z1 = -1e300, z2 = -1e300, z3 = -1e300;
    int m1 = 0, m2 = 0, m3 = 0;
    for (int m = 0; m < 49; m++) {
        const float4* cr = (const float4*)(cf32 + m * 16);
        float dot = 0.f;
        #pragma unroll
        for (int q = 0; q < 4; q++) {
            float4 w = cr[q];
            dot = __fmaf_rn(w.x, ffn[4*q+0], dot);
            dot = __fmaf_rn(w.y, ffn[4*q+1], dot);
            dot = __fmaf_rn(w.z, ffn[4*q+2], dot);
            dot = __fmaf_rn(w.w, ffn[4*q+3], dot);
        }
        if (dot >= thr) {
            double dd = 0.0;
            #pragma unroll
            for (int cc = 0; cc < 16; cc++)
                dd = fma(cfd[m*16+cc], fsd[cc * FSTRIDE + t], dd);
            double z = beta + alpha * (dd * invf);
            if (z > z1)      { z3 = z2; m3 = m2; z2 = z1; m2 = m1; z1 = z; m1 = m; }
            else if (z > z2) { z3 = z2; m3 = m2; z2 = z;  m2 = m; }
            else if (z > z3) { z3 = z;  m3 = m; }
        }
    }
    // fp32-sigmoid collapse tie rule (identical to passing rounds)
    float s1f = (float)(1.0 / (1.0 + exp(-z1)));
    int bm = m1;
    if (z1 - z2 < 1e-5) {
        float s2f = (float)(1.0 / (1.0 + exp(-z2)));
        if (s2f == s1f && m2 < bm) bm = m2;
        if (z1 - z3 < 1e-5) {
            float s3f = (float)(1.0 / (1.0 + exp(-z3)));
            if (s3f == s1f && m3 < bm) bm = m3;
        }
    }
    const float s = s1f;

    // ---- aggregate ----
    atomicAdd(&agd[bm], s);
    #pragma unroll
    for (int cc = 0; cc < 16; cc++)
        atomicAdd(&agn[bm * 16 + cc], s * vs[cc * VSTRIDE + t]);
    __syncthreads();

    for (int it = t; it < 784; it += 256) {
        int m = it >> 4;
        agn[it] = (agn[it] + vc[it]) / (agd[m] + 1.f);
    }
    __syncthreads();

    // ---- load p weights into the (now dead) shared buffer ----
    for (int i = t; i < 4096; i += 256) {
        int cc = i >> 8, o = i & 255;
        pwt[i] = pw[o * CMID + cc];
    }
    __syncthreads();

    // ---- Stage D: mid[n] = s*agg[m*]; y = pw @ mid + pb (packed f32x2) ----
    unsigned long long ocd[16];
    #pragma unroll
    for (int cc = 0; cc < 16; cc++) {
        float o = s * agn[bm * 16 + cc];
        ocd[cc] = pk2(o, o);
    }
    float* yb = out + (size_t)batch * COUT * HW
                    + (size_t)(gx * 16 + pr) * WIDTH + (gy * 16 + pc);
    #pragma unroll 4
    for (int og = 0; og < 64; og++) {
        float4 pbv = __ldg((const float4*)(pbg + og * 4));
        unsigned long long a0 = pk2(pbv.x, pbv.y);
        unsigned long long a1 = pk2(pbv.z, pbv.w);
        #pragma unroll
        for (int cc = 0; cc < 16; cc++) {
            ulonglong2 w = *(const ulonglong2*)(pwt + cc * 256 + og * 4);
            a0 = ffma2(ocd[cc], w.x, a0);
            a1 = ffma2(ocd[cc], w.y, a1);
        }
        float2 r0 = upk(a0), r1 = upk(a1);
        yb[(size_t)(og*4 + 0) * HW] = r0.x;
        yb[(size_t)(og*4 + 1) * HW] = r0.y;
        yb[(size_t)(og*4 + 2) * HW] = r1.x;
        yb[(size_t)(og*4 + 3) * HW] = r1.y;
    }
}

extern "C" void kernel_launch(void* const* d_in, const int* in_sizes, int n_in,
                              void* d_out, int out_size) {
    const float* x   = (const float*)d_in[0];
    const float* fw  = (const float*)d_in[1];
    const float* fb  = (const float*)d_in[2];
    const float* vw  = (const float*)d_in[3];
    const float* vb  = (const float*)d_in[4];
    const float* pw  = (const float*)d_in[5];
    const float* pb  = (const float*)d_in[6];
    const float* sa  = (const float*)d_in[7];
    const float* sb  = (const float*)d_in[8];
    float* out = (float*)d_out;

    cudaFuncSetAttribute(lc_kernel, cudaFuncAttributeMaxDynamicSharedMemorySize,
                         SMEM_BYTES);
    lc_kernel<<<NBLK, 256, SMEM_BYTES>>>(x, fw, fb, vw, vb, pw, pb, sa, sb, out);
}

// round 7
// speedup vs baseline: 3.7931x; 1.3504x over previous
#include <cuda_runtime.h>
#include <math.h>

// Problem constants
#define CIN    128
#define CMID   16
#define COUT   256
#define HW     12544
#define WIDTH  112
#define NBLK   784

// Pooling segments 16 -> 7 (overlapping avg pool)
__constant__ int   SEG_S[7] = {0, 2, 4, 6, 9, 11, 13};
__constant__ int   SEG_E[7] = {3, 5, 7, 10, 12, 14, 16};
__constant__ float SEG_I[7] = {1.f/3.f, 1.f/3.f, 1.f/3.f, 0.25f, 1.f/3.f, 1.f/3.f, 1.f/3.f};

// ---- packed f32x2 helpers (sm_103a, PTX-only) ----
__device__ __forceinline__ unsigned long long pk2(float a, float b) {
    unsigned long long r;
    asm("mov.b64 %0, {%1, %2};" : "=l"(r) : "f"(a), "f"(b));
    return r;
}
__device__ __forceinline__ unsigned long long ffma2(unsigned long long a,
                                                    unsigned long long b,
                                                    unsigned long long c) {
    unsigned long long d;
    asm("fma.rn.f32x2 %0, %1, %2, %3;" : "=l"(d) : "l"(a), "l"(b), "l"(c));
    return d;
}
__device__ __forceinline__ unsigned long long fmul2(unsigned long long a,
                                                    unsigned long long b) {
    unsigned long long d;
    asm("mul.rn.f32x2 %0, %1, %2;" : "=l"(d) : "l"(a), "l"(b));
    return d;
}
__device__ __forceinline__ unsigned long long fadd2(unsigned long long a,
                                                    unsigned long long b) {
    unsigned long long d;
    asm("add.rn.f32x2 %0, %1, %2;" : "=l"(d) : "l"(a), "l"(b));
    return d;
}
__device__ __forceinline__ float2 upk(unsigned long long v) {
    float2 f;
    asm("mov.b64 {%0, %1}, %2;" : "=f"(f.x), "=f"(f.y) : "l"(v));
    return f;
}

#define SGNMASK 0x8000000080000000ULL
#define OFFSET_F 16384.0f

// Exact compensated accumulate (fallback path only).
__device__ __forceinline__ void dfacc2(unsigned long long& hi, unsigned long long& lo,
                                       unsigned long long xd, unsigned long long w) {
    unsigned long long ph = fmul2(xd, w);
    unsigned long long pl = ffma2(xd, w, ph ^ SGNMASK);
    unsigned long long s  = fadd2(hi, ph);
    unsigned long long d  = fadd2(hi, s ^ SGNMASK);
    unsigned long long e  = fadd2(d, ph);
    lo = fadd2(lo, fadd2(e, pl));
    hi = s;
}

// Shared memory byte-offsets
#define FSTR 257
#define OFF_R0    0                          // union: fs float[16*257] (common)
                                             //        fsd double[16*257] (fallback)
#define OFF_CFD   (OFF_R0 + 16*FSTR*8)       // double[784] exact centers (fallback)
#define OFF_WBUF  (OFF_CFD + 784*8)          // float[4096] time-shared:
                                             //  A: wsf[0:2048] wsv[2048:4096]
                                             //  B/C: vc[0:784] cf32[784:1568]
                                             //  fallback: fw2[1568:3616]
                                             //  D: pwt[0:4096]
#define OFF_VS    (OFF_WBUF + 4096*4)        // float[16*257] v features
#define OFF_AGN   (OFF_VS  + 16*FSTR*4)      // float[784]
#define OFF_AGD   (OFF_AGN + 784*4)          // float[52]
#define OFF_FBS   (OFF_AGD + 52*4)           // float[16]
#define OFF_VBS   (OFF_FBS + 16*4)           // float[16]
#define SMEM_BYTES (OFF_VBS + 16*4)          // 75,472 B -> 3 CTAs/SM

extern "C" __global__ void __launch_bounds__(256, 3)
lc_kernel(const float* __restrict__ x,   const float* __restrict__ fw,
          const float* __restrict__ fb,  const float* __restrict__ vw,
          const float* __restrict__ vb,  const float* __restrict__ pw,
          const float* __restrict__ pbg, const float* __restrict__ salpha,
          const float* __restrict__ sbeta, float* __restrict__ out)
{
    extern __shared__ char smraw[];
    float*  fs   = (float*)(smraw + OFF_R0);        // common path
    double* fsd  = (double*)(smraw + OFF_R0);       // fallback (overwrites fs)
    double* cfd  = (double*)(smraw + OFF_CFD);
    float*  wbuf = (float*)(smraw + OFF_WBUF);
    float*  vs   = (float*)(smraw + OFF_VS);
    float*  agn  = (float*)(smraw + OFF_AGN);
    float*  agd  = (float*)(smraw + OFF_AGD);
    float*  fbs  = (float*)(smraw + OFF_FBS);
    float*  vbs  = (float*)(smraw + OFF_VBS);
    float*  wsf  = wbuf;             // stage A
    float*  wsv  = wbuf + 2048;      // stage A
    float*  vc   = wbuf;             // stages B..merge
    float*  cf32 = wbuf + 784;       // stages norm..C (+fallback prefilter)
    float*  fw2  = wbuf + 1568;      // fallback f-weight reload
    float*  pwt  = wbuf;             // stage D

    const int t = threadIdx.x;
    const int b = blockIdx.x;
    const int batch = b / 49;
    const int g = b - batch * 49;
    const int gx = g / 7, gy = g - (g / 7) * 7;
    const int pr = t >> 4, pc = t & 15;

    // ---- stage A weights into smem ----
    for (int i = t; i < 2048; i += 256) {
        int c = i >> 4, o = i & 15;
        wsf[i] = fw[o * CIN + c];
        wsv[i] = vw[o * CIN + c];
    }
    if (t < 16) { fbs[t] = fb[t]; vbs[t] = vb[t]; }
    for (int i = t; i < 784; i += 256) agn[i] = 0.f;
    if (t < 49) agd[t] = 0.f;
    __syncthreads();

    // ---- Stage A (common): f and v in plain packed fp32 ----
    const float* xb = x + (size_t)batch * COUT * HW
                        + (size_t)(gx * 16 + pr) * WIDTH + (gy * 16 + pc);
    {
        unsigned long long fa[8], va[8];
        #pragma unroll
        for (int j = 0; j < 8; j++) { fa[j] = 0ull; va[j] = 0ull; }

        #pragma unroll 8
        for (int c = 0; c < CIN; c++) {
            float x1 = __ldg(xb + (size_t)c * HW);
            float x2 = __ldg(xb + (size_t)(c + CIN) * HW);
            unsigned long long x1d = pk2(x1, x1);
            unsigned long long x2d = pk2(x2, x2);
            const ulonglong2* wf = (const ulonglong2*)(wsf + c * 16);
            const ulonglong2* wv = (const ulonglong2*)(wsv + c * 16);
            #pragma unroll
            for (int j = 0; j < 4; j++) {
                ulonglong2 a = wf[j];
                fa[2*j]   = ffma2(x1d, a.x, fa[2*j]);
                fa[2*j+1] = ffma2(x1d, a.y, fa[2*j+1]);
                ulonglong2 bw = wv[j];
                va[2*j]   = ffma2(x2d, bw.x, va[2*j]);
                va[2*j+1] = ffma2(x2d, bw.y, va[2*j+1]);
            }
        }
        #pragma unroll
        for (int j = 0; j < 8; j++) {
            float2 fv = upk(fa[j]), vv = upk(va[j]);
            fs[(2*j)   * FSTR + t] = fv.x + fbs[2*j];
            fs[(2*j+1) * FSTR + t] = fv.y + fbs[2*j+1];
            vs[(2*j)   * FSTR + t] = vv.x + vbs[2*j];
            vs[(2*j+1) * FSTR + t] = vv.y + vbs[2*j+1];
        }
    }
    __syncthreads();

    // ---- Stage B: fp32 pooling for centers (cf32) and value centers (vc) ----
    for (int it = t; it < 1568; it += 256) {
        int half = it >= 784;
        int rem = half ? it - 784 : it;
        int m = rem >> 4, cc = rem & 15;
        int i = m / 7, jj = m - i * 7;
        const float* src = half ? vs : fs;
        float ssum = 0.f;
        for (int r = SEG_S[i]; r < SEG_E[i]; r++)
            for (int q = SEG_S[jj]; q < SEG_E[jj]; q++)
                ssum += src[cc * FSTR + r * 16 + q];
        ssum *= SEG_I[i] * SEG_I[jj];
        if (half) vc[rem] = ssum; else cf32[rem] = ssum;
    }
    __syncthreads();

    // ---- normalize centers (fp32) ----
    if (t < 49) {
        float ss = 0.f;
        #pragma unroll
        for (int cc = 0; cc < 16; cc++) {
            float v = cf32[t*16+cc];
            ss = __fmaf_rn(v, v, ss);
        }
        float inv = 1.f / fmaxf(sqrtf(ss), 1e-12f);
        #pragma unroll
        for (int cc = 0; cc < 16; cc++) cf32[t*16+cc] *= inv;
    }
    __syncthreads();

    // ---- Stage C (common): fp32 dots, top-2 z, gap test ----
    float ffn[16];
    {
        float ss = 0.f;
        #pragma unroll
        for (int cc = 0; cc < 16; cc++) {
            float v = fs[cc * FSTR + t];
            ffn[cc] = v;
            ss = __fmaf_rn(v, v, ss);
        }
        float inv = 1.f / fmaxf(sqrtf(ss), 1e-12f);
        #pragma unroll
        for (int cc = 0; cc < 16; cc++) ffn[cc] *= inv;
    }
    const float alphaf = __ldg(salpha);
    const float betaf  = __ldg(sbeta);

    float z1 = -1e30f, z2 = -1e30f;
    int bm = 0;
    for (int m = 0; m < 49; m++) {
        const float4* cr = (const float4*)(cf32 + m * 16);
        float dot = 0.f;
        #pragma unroll
        for (int q = 0; q < 4; q++) {
            float4 w = cr[q];
            dot = __fmaf_rn(w.x, ffn[4*q+0], dot);
            dot = __fmaf_rn(w.y, ffn[4*q+1], dot);
            dot = __fmaf_rn(w.z, ffn[4*q+2], dot);
            dot = __fmaf_rn(w.w, ffn[4*q+3], dot);
        }
        float z = betaf + alphaf * dot;
        if (z > z1) { z2 = z1; z1 = z; bm = m; }
        else if (z > z2) { z2 = z; }
    }
    float s = 1.f / (1.f + expf(-z1));

    // ---- per-CTA vote: any pixel too close to call? -> exact fallback ----
    if (__syncthreads_or((z1 - z2) < 1e-4f)) {
        // reload f weights (wsf region was overwritten by vc/cf32)
        for (int i = t; i < 2048; i += 256) {
            int c = i >> 4, o = i & 15;
            fw2[i] = fw[o * CIN + c];
        }
        __syncthreads();

        // exact f via offset-fast2sum df (fs region becomes fsd fp64)
        unsigned long long fhi[8], flo[8];
        #pragma unroll
        for (int j = 0; j < 8; j++) { fhi[j] = pk2(OFFSET_F, OFFSET_F); flo[j] = 0ull; }
        #pragma unroll 4
        for (int c = 0; c < CIN; c++) {
            float x1 = __ldg(xb + (size_t)c * HW);
            unsigned long long x1d = pk2(x1, x1);
            const ulonglong2* wf = (const ulonglong2*)(fw2 + c * 16);
            #pragma unroll
            for (int j = 0; j < 4; j++) {
                ulonglong2 a = wf[j];
                dfacc2(fhi[2*j],   flo[2*j],   x1d, a.x);
                dfacc2(fhi[2*j+1], flo[2*j+1], x1d, a.y);
            }
        }
        __syncthreads();   // all reads of fs done before overwrite
        #pragma unroll
        for (int j = 0; j < 8; j++) {
            float2 h = upk(fhi[j]), l = upk(flo[j]);
            fsd[(2*j)   * FSTR + t] =
                ((double)__fadd_rn(h.x, -OFFSET_F) + (double)l.x) + (double)fbs[2*j];
            fsd[(2*j+1) * FSTR + t] =
                ((double)__fadd_rn(h.y, -OFFSET_F) + (double)l.y) + (double)fbs[2*j+1];
        }
        __syncthreads();

        // fp64 pooled centers
        for (int it = t; it < 784; it += 256) {
            int m = it >> 4, cc = it & 15;
            int i = m / 7, jj = m - i * 7;
            double ssum = 0.0;
            for (int r = SEG_S[i]; r < SEG_E[i]; r++)
                for (int q = SEG_S[jj]; q < SEG_E[jj]; q++)
                    ssum += fsd[cc * FSTR + r * 16 + q];
            cfd[it] = ssum * (double)SEG_I[i] * (double)SEG_I[jj];
        }
        __syncthreads();
        if (t < 49) {
            double ss = 0.0;
            #pragma unroll
            for (int cc = 0; cc < 16; cc++) { double v = cfd[t*16+cc]; ss = fma(v, v, ss); }
            double inv = 1.0 / fmax(sqrt(ss), 1e-12);
            #pragma unroll
            for (int cc = 0; cc < 16; cc++) cfd[t*16+cc] *= inv;
        }
        __syncthreads();

        // exact per-pixel norm + prefiltered exact dots + collapse tie rule
        double invf;
        {
            double ss = 0.0;
            #pragma unroll
            for (int cc = 0; cc < 16; cc++) {
                double v = fsd[cc * FSTR + t];
                ss = fma(v, v, ss);
            }
            invf = 1.0 / fmax(sqrt(ss), 1e-12);
        }
        const double alpha = (double)alphaf;
        const double beta  = (double)betaf;

        float mx32 = -1e30f;
        for (int m = 0; m < 49; m++) {
            const float4* cr = (const float4*)(cf32 + m * 16);
            float dot = 0.f;
            #pragma unroll
            for (int q = 0; q < 4; q++) {
                float4 w = cr[q];
                dot = __fmaf_rn(w.x, ffn[4*q+0], dot);
                dot = __fmaf_rn(w.y, ffn[4*q+1], dot);
                dot = __fmaf_rn(w.z, ffn[4*q+2], dot);
                dot = __fmaf_rn(w.w, ffn[4*q+3], dot);
            }
            mx32 = fmaxf(mx32, dot);
        }
        const float thr = mx32 - 1e-4f;
        double dz1 = -1e300, dz2 = -1e300, dz3 = -1e300;
        int m1 = 0, m2 = 0, m3 = 0;
        for (int m = 0; m < 49; m++) {
            const float4* cr = (const float4*)(cf32 + m * 16);
            float dot = 0.f;
            #pragma unroll
            for (int q = 0; q < 4; q++) {
                float4 w = cr[q];
                dot = __fmaf_rn(w.x, ffn[4*q+0], dot);
                dot = __fmaf_rn(w.y, ffn[4*q+1], dot);
                dot = __fmaf_rn(w.z, ffn[4*q+2], dot);
                dot = __fmaf_rn(w.w, ffn[4*q+3], dot);
            }
            if (dot >= thr) {
                double dd = 0.0;
                #pragma unroll
                for (int cc = 0; cc < 16; cc++)
                    dd = fma(cfd[m*16+cc], fsd[cc * FSTR + t], dd);
                double z = beta + alpha * (dd * invf);
                if (z > dz1)      { dz3 = dz2; m3 = m2; dz2 = dz1; m2 = m1; dz1 = z; m1 = m; }
                else if (z > dz2) { dz3 = dz2; m3 = m2; dz2 = z;  m2 = m; }
                else if (z > dz3) { dz3 = z;  m3 = m; }
            }
        }
        float s1f = (float)(1.0 / (1.0 + exp(-dz1)));
        bm = m1;
        if (dz1 - dz2 < 1e-5) {
            float s2f = (float)(1.0 / (1.0 + exp(-dz2)));
            if (s2f == s1f && m2 < bm) bm = m2;
            if (dz1 - dz3 < 1e-5) {
                float s3f = (float)(1.0 / (1.0 + exp(-dz3)));
                if (s3f == s1f && m3 < bm) bm = m3;
            }
        }
        s = s1f;
        __syncthreads();
    }

    // ---- aggregate ----
    atomicAdd(&agd[bm], s);
    #pragma unroll
    for (int cc = 0; cc < 16; cc++)
        atomicAdd(&agn[bm * 16 + cc], s * vs[cc * FSTR + t]);
    __syncthreads();

    for (int it = t; it < 784; it += 256) {
        int m = it >> 4;
        agn[it] = (agn[it] + vc[it]) / (agd[m] + 1.f);
    }
    __syncthreads();

    // ---- load p weights (overwrites wbuf) ----
    for (int i = t; i < 4096; i += 256) {
        int cc = i >> 8, o = i & 255;
        pwt[i] = pw[o * CMID + cc];
    }
    __syncthreads();

    // ---- Stage D: mid[n] = s*agg[m*]; y = pw @ mid + pb (packed f32x2) ----
    unsigned long long ocd[16];
    #pragma unroll
    for (int cc = 0; cc < 16; cc++) {
        float o = s * agn[bm * 16 + cc];
        ocd[cc] = pk2(o, o);
    }
    float* yb = out + (size_t)batch * COUT * HW
                    + (size_t)(gx * 16 + pr) * WIDTH + (gy * 16 + pc);
    #pragma unroll 4
    for (int og = 0; og < 64; og++) {
        float4 pbv = __ldg((const float4*)(pbg + og * 4));
        unsigned long long a0 = pk2(pbv.x, pbv.y);
        unsigned long long a1 = pk2(pbv.z, pbv.w);
        #pragma unroll
        for (int cc = 0; cc < 16; cc++) {
            ulonglong2 w = *(const ulonglong2*)(pwt + cc * 256 + og * 4);
            a0 = ffma2(ocd[cc], w.x, a0);
            a1 = ffma2(ocd[cc], w.y, a1);
        }
        float2 r0 = upk(a0), r1 = upk(a1);
        yb[(size_t)(og*4 + 0) * HW] = r0.x;
        yb[(size_t)(og*4 + 1) * HW] = r0.y;
        yb[(size_t)(og*4 + 2) * HW] = r1.x;
        yb[(size_t)(og*4 + 3) * HW] = r1.y;
    }
}

extern "C" void kernel_launch(void* const* d_in, const int* in_sizes, int n_in,
                              void* d_out, int out_size) {
    const float* x   = (const float*)d_in[0];
    const float* fw  = (const float*)d_in[1];
    const float* fb  = (const float*)d_in[2];
    const float* vw  = (const float*)d_in[3];
    const float* vb  = (const float*)d_in[4];
    const float* pw  = (const float*)d_in[5];
    const float* pb  = (const float*)d_in[6];
    const float* sa  = (const float*)d_in[7];
    const float* sb  = (const float*)d_in[8];
    float* out = (float*)d_out;

    cudaFuncSetAttribute(lc_kernel, cudaFuncAttributeMaxDynamicSharedMemorySize,
                         SMEM_BYTES);
    lc_kernel<<<NBLK, 256, SMEM_BYTES>>>(x, fw, fb, vw, vb, pw, pb, sa, sb, out);
}

// round 8
// speedup vs baseline: 4.1289x; 1.0885x over previous
#include <cuda_runtime.h>
#include <math.h>

// Problem constants
#define CIN    128
#define CMID   16
#define COUT   256
#define HW     12544
#define WIDTH  112
#define NBLK   784
#define NTHR   512

// Pooling segments 16 -> 7 (overlapping avg pool)
__constant__ int   SEG_S[7] = {0, 2, 4, 6, 9, 11, 13};
__constant__ int   SEG_E[7] = {3, 5, 7, 10, 12, 14, 16};
__constant__ float SEG_I[7] = {1.f/3.f, 1.f/3.f, 1.f/3.f, 0.25f, 1.f/3.f, 1.f/3.f, 1.f/3.f};

// ---- packed f32x2 helpers (sm_103a, PTX-only) ----
__device__ __forceinline__ unsigned long long pk2(float a, float b) {
    unsigned long long r;
    asm("mov.b64 %0, {%1, %2};" : "=l"(r) : "f"(a), "f"(b));
    return r;
}
__device__ __forceinline__ unsigned long long ffma2(unsigned long long a,
                                                    unsigned long long b,
                                                    unsigned long long c) {
    unsigned long long d;
    asm("fma.rn.f32x2 %0, %1, %2, %3;" : "=l"(d) : "l"(a), "l"(b), "l"(c));
    return d;
}
__device__ __forceinline__ unsigned long long fmul2(unsigned long long a,
                                                    unsigned long long b) {
    unsigned long long d;
    asm("mul.rn.f32x2 %0, %1, %2;" : "=l"(d) : "l"(a), "l"(b));
    return d;
}
__device__ __forceinline__ unsigned long long fadd2(unsigned long long a,
                                                    unsigned long long b) {
    unsigned long long d;
    asm("add.rn.f32x2 %0, %1, %2;" : "=l"(d) : "l"(a), "l"(b));
    return d;
}
__device__ __forceinline__ float2 upk(unsigned long long v) {
    float2 f;
    asm("mov.b64 {%0, %1}, %2;" : "=f"(f.x), "=f"(f.y) : "l"(v));
    return f;
}

#define SGNMASK 0x8000000080000000ULL
#define OFFSET_F 16384.0f

// Exact compensated accumulate (fallback path only).
__device__ __forceinline__ void dfacc2(unsigned long long& hi, unsigned long long& lo,
                                       unsigned long long xd, unsigned long long w) {
    unsigned long long ph = fmul2(xd, w);
    unsigned long long pl = ffma2(xd, w, ph ^ SGNMASK);
    unsigned long long s  = fadd2(hi, ph);
    unsigned long long d  = fadd2(hi, s ^ SGNMASK);
    unsigned long long e  = fadd2(d, ph);
    lo = fadd2(lo, fadd2(e, pl));
    hi = s;
}

// Shared memory byte-offsets
#define FSTR 257     // stride (floats for fs/vs, doubles for fsd)
#define MSTR 18      // midT stride (floats), conflict-dodged, 8B-aligned rows
#define OFF_R0    0                          // union: fs float[16*257] (common)
                                             //        fsd double[16*257] (fallback)
                                             //        midT float[256*18] (stage D)
#define OFF_CFD   (OFF_R0 + 16*FSTR*8)       // double[784] exact centers (fallback)
#define OFF_WBUF  (OFF_CFD + 784*8)          // float[4096] time-shared:
                                             //  A: wsf[0:2048] wsv[2048:4096]
                                             //  B/C: vc[0:784] cf32[784:1568]
                                             //  fallback: fw2[1568:3616]
                                             //  D: pwt2[0:4096] (pw as-is, [o][cc])
#define OFF_VS    (OFF_WBUF + 4096*4)        // float[16*257] v features
#define OFF_AGN   (OFF_VS  + 16*FSTR*4)      // float[784]
#define OFF_AGD   (OFF_AGN + 784*4)          // float[52]
#define OFF_FBS   (OFF_AGD + 52*4)           // float[16]
#define OFF_VBS   (OFF_FBS + 16*4)           // float[16]
#define OFF_PBS   (OFF_VBS + 16*4)           // float[256]
#define SMEM_BYTES (OFF_PBS + 256*4)         // 76,496 B -> 2 CTAs/SM @512thr

extern "C" __global__ void __launch_bounds__(NTHR, 2)
lc_kernel(const float* __restrict__ x,   const float* __restrict__ fw,
          const float* __restrict__ fb,  const float* __restrict__ vw,
          const float* __restrict__ vb,  const float* __restrict__ pw,
          const float* __restrict__ pbg, const float* __restrict__ salpha,
          const float* __restrict__ sbeta, float* __restrict__ out)
{
    extern __shared__ char smraw[];
    float*  fs   = (float*)(smraw + OFF_R0);
    double* fsd  = (double*)(smraw + OFF_R0);
    float*  midT = (float*)(smraw + OFF_R0);
    double* cfd  = (double*)(smraw + OFF_CFD);
    float*  wbuf = (float*)(smraw + OFF_WBUF);
    float*  vs   = (float*)(smraw + OFF_VS);
    float*  agn  = (float*)(smraw + OFF_AGN);
    float*  agd  = (float*)(smraw + OFF_AGD);
    float*  fbs  = (float*)(smraw + OFF_FBS);
    float*  vbs  = (float*)(smraw + OFF_VBS);
    float*  pbs  = (float*)(smraw + OFF_PBS);
    float*  wsf  = wbuf;
    float*  wsv  = wbuf + 2048;
    float*  vc   = wbuf;
    float*  cf32 = wbuf + 784;
    float*  fw2  = wbuf + 1568;
    float*  pwt2 = wbuf;

    const int t = threadIdx.x;
    const int b = blockIdx.x;
    const int batch = b / 49;
    const int g = b - batch * 49;
    const int gx = g / 7, gy = g - (g / 7) * 7;

    // ---- stage A weights + biases into smem ----
    for (int i = t; i < 2048; i += NTHR) {
        int c = i >> 4, o = i & 15;
        wsf[i] = fw[o * CIN + c];
        wsv[i] = vw[o * CIN + c];
    }
    if (t < 16) { fbs[t] = fb[t]; vbs[t] = vb[t]; }
    if (t < 256) pbs[t] = pbg[t];
    for (int i = t; i < 784; i += NTHR) agn[i] = 0.f;
    if (t < 49) agd[t] = 0.f;
    __syncthreads();

    // ---- Stage A: warps 0-7 -> f, warps 8-15 -> v (1 pixel, 128 ch each) ----
    const int px  = t & 255;             // pixel
    const int prj = t >> 8;              // 0 = f, 1 = v
    const int apr = px >> 4, apc = px & 15;
    const float* xa = x + (size_t)batch * COUT * HW + (size_t)prj * CIN * HW
                        + (size_t)(gx * 16 + apr) * WIDTH + (gy * 16 + apc);
    const float* wsel = prj ? wsv : wsf;
    {
        unsigned long long acc[8];
        #pragma unroll
        for (int j = 0; j < 8; j++) acc[j] = 0ull;
        #pragma unroll 8
        for (int c = 0; c < CIN; c++) {
            float xv = __ldg(xa + (size_t)c * HW);
            unsigned long long xd = pk2(xv, xv);
            const ulonglong2* wr = (const ulonglong2*)(wsel + c * 16);
            #pragma unroll
            for (int j = 0; j < 4; j++) {
                ulonglong2 a = wr[j];
                acc[2*j]   = ffma2(xd, a.x, acc[2*j]);
                acc[2*j+1] = ffma2(xd, a.y, acc[2*j+1]);
            }
        }
        float* dst = prj ? vs : fs;
        const float* bsel = prj ? vbs : fbs;
        #pragma unroll
        for (int j = 0; j < 8; j++) {
            float2 v = upk(acc[j]);
            dst[(2*j)   * FSTR + px] = v.x + bsel[2*j];
            dst[(2*j+1) * FSTR + px] = v.y + bsel[2*j+1];
        }
    }
    __syncthreads();

    // ---- Stage B: fp32 pooling (centers cf32, value centers vc) ----
    for (int it = t; it < 1568; it += NTHR) {
        int half = it >= 784;
        int rem = half ? it - 784 : it;
        int m = rem >> 4, cc = rem & 15;
        int i = m / 7, jj = m - i * 7;
        const float* src = half ? vs : fs;
        float ssum = 0.f;
        for (int r = SEG_S[i]; r < SEG_E[i]; r++)
            for (int q = SEG_S[jj]; q < SEG_E[jj]; q++)
                ssum += src[cc * FSTR + r * 16 + q];
        ssum *= SEG_I[i] * SEG_I[jj];
        if (half) vc[rem] = ssum; else cf32[rem] = ssum;
    }
    __syncthreads();

    if (t < 49) {
        float ss = 0.f;
        #pragma unroll
        for (int cc = 0; cc < 16; cc++) {
            float v = cf32[t*16+cc];
            ss = __fmaf_rn(v, v, ss);
        }
        float inv = 1.f / fmaxf(sqrtf(ss), 1e-12f);
        #pragma unroll
        for (int cc = 0; cc < 16; cc++) cf32[t*16+cc] *= inv;
    }
    __syncthreads();

    // ---- Stage C (common, lower 256 threads): fp32 dots, top-2, gap test ----
    float ffn[16];
    float z1 = 1e30f, z2 = 0.f;          // upper threads: gap huge -> no vote
    int bm = 0;
    float s = 0.f;
    const float alphaf = __ldg(salpha);
    const float betaf  = __ldg(sbeta);
    if (t < 256) {
        float ss = 0.f;
        #pragma unroll
        for (int cc = 0; cc < 16; cc++) {
            float v = fs[cc * FSTR + t];
            ffn[cc] = v;
            ss = __fmaf_rn(v, v, ss);
        }
        float inv = 1.f / fmaxf(sqrtf(ss), 1e-12f);
        #pragma unroll
        for (int cc = 0; cc < 16; cc++) ffn[cc] *= inv;

        z1 = -1e30f; z2 = -1e30f;
        for (int m = 0; m < 49; m++) {
            const float4* cr = (const float4*)(cf32 + m * 16);
            float dot = 0.f;
            #pragma unroll
            for (int q = 0; q < 4; q++) {
                float4 w = cr[q];
                dot = __fmaf_rn(w.x, ffn[4*q+0], dot);
                dot = __fmaf_rn(w.y, ffn[4*q+1], dot);
                dot = __fmaf_rn(w.z, ffn[4*q+2], dot);
                dot = __fmaf_rn(w.w, ffn[4*q+3], dot);
            }
            float z = betaf + alphaf * dot;
            if (z > z1) { z2 = z1; z1 = z; bm = m; }
            else if (z > z2) { z2 = z; }
        }
        s = 1.f / (1.f + expf(-z1));
    }

    // ---- per-CTA vote: exact fallback if any pixel too close to call ----
    if (__syncthreads_or((z1 - z2) < 1e-4f)) {
        for (int i = t; i < 2048; i += NTHR) {
            int c = i >> 4, o = i & 15;
            fw2[i] = fw[o * CIN + c];
        }
        __syncthreads();

        unsigned long long fhi[8], flo[8];
        if (t < 256) {
            #pragma unroll
            for (int j = 0; j < 8; j++) { fhi[j] = pk2(OFFSET_F, OFFSET_F); flo[j] = 0ull; }
            const float* xf = x + (size_t)batch * COUT * HW
                                + (size_t)(gx * 16 + apr) * WIDTH + (gy * 16 + apc);
            #pragma unroll 4
            for (int c = 0; c < CIN; c++) {
                float x1 = __ldg(xf + (size_t)c * HW);
                unsigned long long x1d = pk2(x1, x1);
                const ulonglong2* wf = (const ulonglong2*)(fw2 + c * 16);
                #pragma unroll
                for (int j = 0; j < 4; j++) {
                    ulonglong2 a = wf[j];
                    dfacc2(fhi[2*j],   flo[2*j],   x1d, a.x);
                    dfacc2(fhi[2*j+1], flo[2*j+1], x1d, a.y);
                }
            }
        }
        __syncthreads();     // all fs readers done before fp64 overwrite
        if (t < 256) {
            #pragma unroll
            for (int j = 0; j < 8; j++) {
                float2 h = upk(fhi[j]), l = upk(flo[j]);
                fsd[(2*j)   * FSTR + t] =
                    ((double)__fadd_rn(h.x, -OFFSET_F) + (double)l.x) + (double)fbs[2*j];
                fsd[(2*j+1) * FSTR + t] =
                    ((double)__fadd_rn(h.y, -OFFSET_F) + (double)l.y) + (double)fbs[2*j+1];
            }
        }
        __syncthreads();

        for (int it = t; it < 784; it += NTHR) {
            int m = it >> 4, cc = it & 15;
            int i = m / 7, jj = m - i * 7;
            double ssum = 0.0;
            for (int r = SEG_S[i]; r < SEG_E[i]; r++)
                for (int q = SEG_S[jj]; q < SEG_E[jj]; q++)
                    ssum += fsd[cc * FSTR + r * 16 + q];
            cfd[it] = ssum * (double)SEG_I[i] * (double)SEG_I[jj];
        }
        __syncthreads();
        if (t < 49) {
            double ss = 0.0;
            #pragma unroll
            for (int cc = 0; cc < 16; cc++) { double v = cfd[t*16+cc]; ss = fma(v, v, ss); }
            double inv = 1.0 / fmax(sqrt(ss), 1e-12);
            #pragma unroll
            for (int cc = 0; cc < 16; cc++) cfd[t*16+cc] *= inv;
        }
        __syncthreads();

        if (t < 256) {
            double invf;
            {
                double ss = 0.0;
                #pragma unroll
                for (int cc = 0; cc < 16; cc++) {
                    double v = fsd[cc * FSTR + t];
                    ss = fma(v, v, ss);
                }
                invf = 1.0 / fmax(sqrt(ss), 1e-12);
            }
            const double alpha = (double)alphaf;
            const double beta  = (double)betaf;

            float mx32 = -1e30f;
            for (int m = 0; m < 49; m++) {
                const float4* cr = (const float4*)(cf32 + m * 16);
                float dot = 0.f;
                #pragma unroll
                for (int q = 0; q < 4; q++) {
                    float4 w = cr[q];
                    dot = __fmaf_rn(w.x, ffn[4*q+0], dot);
                    dot = __fmaf_rn(w.y, ffn[4*q+1], dot);
                    dot = __fmaf_rn(w.z, ffn[4*q+2], dot);
                    dot = __fmaf_rn(w.w, ffn[4*q+3], dot);
                }
                mx32 = fmaxf(mx32, dot);
            }
            const float thr = mx32 - 1e-4f;
            double dz1 = -1e300, dz2 = -1e300, dz3 = -1e300;
            int m1 = 0, m2 = 0, m3 = 0;
            for (int m = 0; m < 49; m++) {
                const float4* cr = (const float4*)(cf32 + m * 16);
                float dot = 0.f;
                #pragma unroll
                for (int q = 0; q < 4; q++) {
                    float4 w = cr[q];
                    dot = __fmaf_rn(w.x, ffn[4*q+0], dot);
                    dot = __fmaf_rn(w.y, ffn[4*q+1], dot);
                    dot = __fmaf_rn(w.z, ffn[4*q+2], dot);
                    dot = __fmaf_rn(w.w, ffn[4*q+3], dot);
                }
                if (dot >= thr) {
                    double dd = 0.0;
                    #pragma unroll
                    for (int cc = 0; cc < 16; cc++)
                        dd = fma(cfd[m*16+cc], fsd[cc * FSTR + t], dd);
                    double z = beta + alpha * (dd * invf);
                    if (z > dz1)      { dz3 = dz2; m3 = m2; dz2 = dz1; m2 = m1; dz1 = z; m1 = m; }
                    else if (z > dz2) { dz3 = dz2; m3 = m2; dz2 = z;  m2 = m; }
                    else if (z > dz3) { dz3 = z;  m3 = m; }
                }
            }
            float s1f = (float)(1.0 / (1.0 + exp(-dz1)));
            bm = m1;
            if (dz1 - dz2 < 1e-5) {
                float s2f = (float)(1.0 / (1.0 + exp(-dz2)));
                if (s2f == s1f && m2 < bm) bm = m2;
                if (dz1 - dz3 < 1e-5) {
                    float s3f = (float)(1.0 / (1.0 + exp(-dz3)));
                    if (s3f == s1f && m3 < bm) bm = m3;
                }
            }
            s = s1f;
        }
        __syncthreads();
    }

    // ---- aggregate (lower 256 threads) ----
    if (t < 256) {
        atomicAdd(&agd[bm], s);
        #pragma unroll
        for (int cc = 0; cc < 16; cc++)
            atomicAdd(&agn[bm * 16 + cc], s * vs[cc * FSTR + t]);
    }
    __syncthreads();

    for (int it = t; it < 784; it += NTHR) {
        int m = it >> 4;
        agn[it] = (agn[it] + vc[it]) / (agd[m] + 1.f);
    }
    __syncthreads();

    // ---- write midT[n][cc] (transposed; fs region is dead now) ----
    if (t < 256) {
        #pragma unroll
        for (int q = 0; q < 8; q++) {
            float a = s * agn[bm * 16 + 2*q];
            float c = s * agn[bm * 16 + 2*q + 1];
            *(unsigned long long*)(midT + t * MSTR + 2*q) = pk2(a, c);
        }
    }
    // ---- load p weights as-is ([o][cc], row-major) ----
    for (int i = t; i < 1024; i += NTHR)
        ((float4*)pwt2)[i] = ((const float4*)pw)[i];
    __syncthreads();

    // ---- Stage D: thread = (o-group of 64) x (pixel pair); GEMM from regs ----
    {
        const int nid = t & 127, oid = t >> 7;
        const int n0 = 2 * nid;
        unsigned long long midA[8], midB[8];
        #pragma unroll
        for (int q = 0; q < 8; q++) {
            midA[q] = *(const unsigned long long*)(midT + n0 * MSTR + 2*q);
            midB[q] = *(const unsigned long long*)(midT + (n0 + 1) * MSTR + 2*q);
        }
        float* yb = out + (size_t)batch * COUT * HW
                        + (size_t)(gx * 16 + (n0 >> 4)) * WIDTH + (gy * 16 + (n0 & 15));
        const int obase = oid << 6;
        #pragma unroll 4
        for (int i = 0; i < 64; i++) {
            const int o = obase + i;
            const ulonglong2* wr = (const ulonglong2*)(pwt2 + o * 16);
            unsigned long long aA = 0ull, aB = 0ull;
            #pragma unroll
            for (int q = 0; q < 2; q++) {
                ulonglong2 w = wr[q];
                aA = ffma2(w.x, midA[2*q],   aA);
                aA = ffma2(w.y, midA[2*q+1], aA);
                aB = ffma2(w.x, midB[2*q],   aB);
                aB = ffma2(w.y, midB[2*q+1], aB);
            }
            #pragma unroll
            for (int q = 2; q < 4; q++) {
                ulonglong2 w = wr[q];
                aA = ffma2(w.x, midA[2*q],   aA);
                aA = ffma2(w.y, midA[2*q+1], aA);
                aB = ffma2(w.x, midB[2*q],   aB);
                aB = ffma2(w.y, midB[2*q+1], aB);
            }
            float2 fa = upk(aA), fbv = upk(aB);
            float pbo = pbs[o];
            float2 r;
            r.x = pbo + fa.x + fa.y;
            r.y = pbo + fbv.x + fbv.y;
            *(float2*)(yb + (size_t)o * HW) = r;
        }
    }
}

extern "C" void kernel_launch(void* const* d_in, const int* in_sizes, int n_in,
                              void* d_out, int out_size) {
    const float* x   = (const float*)d_in[0];
    const float* fw  = (const float*)d_in[1];
    const float* fb  = (const float*)d_in[2];
    const float* vw  = (const float*)d_in[3];
    const float* vb  = (const float*)d_in[4];
    const float* pw  = (const float*)d_in[5];
    const float* pb  = (const float*)d_in[6];
    const float* sa  = (const float*)d_in[7];
    const float* sb  = (const float*)d_in[8];
    float* out = (float*)d_out;

    cudaFuncSetAttribute(lc_kernel, cudaFuncAttributeMaxDynamicSharedMemorySize,
                         SMEM_BYTES);
    lc_kernel<<<NBLK, NTHR, SMEM_BYTES>>>(x, fw, fb, vw, vb, pw, pb, sa, sb, out);
}